// round 16
// baseline (speedup 1.0000x reference)
#include <cuda_runtime.h>
#include <cuda_fp16.h>

#define THREADS 256
#define C16 16
#define DIM 96
#define HW (DIM*DIM)
#define DHW (DIM*DIM*DIM)
#define FEATS 512
#define KTOT 1024
#define KPB 512            // k per block (KSPLIT=2)
#define NB 8               // fixed brick edge
// padded strides in uint4 (16B) units: x=1, y=10, z=84
// bank-group(16B): (84*dz + 10*dy + dx) mod 8 = {4dz+2dy+dx} mod 8 -> never 0 for |d|<=1
#define SY 10
#define SZ 84
#define PSV (NB*SZ)        // 672 uint4 per channel-octet slab
#define NOCT 2             // 16 channels = 2 octets (uint4 = 4 x half2)
#define BRICK_E (NOCT*PSV) // 1344 uint4 = 21KB

// Hot accumulate: 8 corners x 2 octets from the smem brick.
__device__ __forceinline__ void brick_accum(
    const uint4* __restrict__ brickq, const int* offs, const float* wgt,
    unsigned long long* acc64)
{
    #pragma unroll
    for (int j = 0; j < 8; j++) {
        const uint4* pj = brickq + offs[j];
        unsigned long long w2pk;
        unsigned int wbits = __float_as_uint(wgt[j]);
        asm("mov.b64 %0, {%1, %1};" : "=l"(w2pk) : "r"(wbits));
        #pragma unroll
        for (int c8 = 0; c8 < NOCT; c8++) {   // LDS.128, immediate c8*PSV*16
            uint4 q = pj[c8 * PSV];
            __half2 h0 = *reinterpret_cast<__half2*>(&q.x);
            __half2 h1 = *reinterpret_cast<__half2*>(&q.y);
            __half2 h2 = *reinterpret_cast<__half2*>(&q.z);
            __half2 h3 = *reinterpret_cast<__half2*>(&q.w);
            float2 f0 = __half22float2(h0);
            float2 f1 = __half22float2(h1);
            float2 f2 = __half22float2(h2);
            float2 f3 = __half22float2(h3);
            unsigned long long v0, v1, v2, v3;
            asm("mov.b64 %0, {%1, %2};" : "=l"(v0) : "f"(f0.x), "f"(f0.y));
            asm("mov.b64 %0, {%1, %2};" : "=l"(v1) : "f"(f1.x), "f"(f1.y));
            asm("mov.b64 %0, {%1, %2};" : "=l"(v2) : "f"(f2.x), "f"(f2.y));
            asm("mov.b64 %0, {%1, %2};" : "=l"(v3) : "f"(f3.x), "f"(f3.y));
            asm("fma.rn.f32x2 %0, %1, %2, %0;" : "+l"(acc64[4*c8])   : "l"(v0), "l"(w2pk));
            asm("fma.rn.f32x2 %0, %1, %2, %0;" : "+l"(acc64[4*c8+1]) : "l"(v1), "l"(w2pk));
            asm("fma.rn.f32x2 %0, %1, %2, %0;" : "+l"(acc64[4*c8+2]) : "l"(v2), "l"(w2pk));
            asm("fma.rn.f32x2 %0, %1, %2, %0;" : "+l"(acc64[4*c8+3]) : "l"(v3), "l"(w2pk));
        }
    }
}

// Cold fallback: out-of-brick (incl. out-of-volume) corners; fp32 global gather.
// Takes RAW (unclamped) indices and pre-zeroed-by-nothing axis weights; applies
// full volume clamp + weight-zero here. Numerically identical to R15's cold path.
__device__ __noinline__ void cold_accum(
    const float* __restrict__ volb,
    int ix0, int ix1, int iy0, int iy1, int iz0, int iz1,
    float wx0, float wx1, float wy0, float wy1, float wz0, float wz1,
    float sg, unsigned long long* acc64)
{
    if ((unsigned)ix0 >= DIM) { wx0 = 0.f; ix0 = (ix0 < 0) ? 0 : DIM-1; }
    if ((unsigned)ix1 >= DIM) { wx1 = 0.f; ix1 = (ix1 < 0) ? 0 : DIM-1; }
    if ((unsigned)iy0 >= DIM) { wy0 = 0.f; iy0 = (iy0 < 0) ? 0 : DIM-1; }
    if ((unsigned)iy1 >= DIM) { wy1 = 0.f; iy1 = (iy1 < 0) ? 0 : DIM-1; }
    if ((unsigned)iz0 >= DIM) { wz0 = 0.f; iz0 = (iz0 < 0) ? 0 : DIM-1; }
    if ((unsigned)iz1 >= DIM) { wz1 = 0.f; iz1 = (iz1 < 0) ? 0 : DIM-1; }
    float wzy00 = wz0*wy0*sg, wzy01 = wz0*wy1*sg;
    float wzy10 = wz1*wy0*sg, wzy11 = wz1*wy1*sg;
    float wgt[8] = { wzy00*wx0, wzy00*wx1, wzy01*wx0, wzy01*wx1,
                     wzy10*wx0, wzy10*wx1, wzy11*wx0, wzy11*wx1 };
    float accf[C16];
    #pragma unroll
    for (int p = 0; p < 8; p++) {
        float lo, hi;
        asm("mov.b64 {%0, %1}, %2;" : "=f"(lo), "=f"(hi) : "l"(acc64[p]));
        accf[2*p] = lo; accf[2*p+1] = hi;
    }
    int r00 = iz0*HW + iy0*DIM, r01 = iz0*HW + iy1*DIM;
    int r10 = iz1*HW + iy0*DIM, r11 = iz1*HW + iy1*DIM;
    int offs[8] = { r00+ix0, r00+ix1, r01+ix0, r01+ix1,
                    r10+ix0, r10+ix1, r11+ix0, r11+ix1 };
    #pragma unroll 1
    for (int j = 0; j < 8; j++) {
        const float* pj = volb + offs[j];
        float w = wgt[j];
        #pragma unroll
        for (int c = 0; c < C16; c++)
            accf[c] = fmaf(w, __ldg(pj + (size_t)c * DHW), accf[c]);
    }
    #pragma unroll
    for (int p = 0; p < 8; p++)
        asm("mov.b64 %0, {%1, %2};" : "=l"(acc64[p]) : "f"(accf[2*p]), "f"(accf[2*p+1]));
}

// Main k-loop, specialized on whether the brick touches the volume border.
// EDGE: clamp-then-check (R15 flow) so near-border samples stay on the hot path.
// !EDGE (74% of blocks): raw-index check, no clamp math on the hot path
// (in-brick => in-volume since brick is interior).
template<bool EDGE>
__device__ __forceinline__ void run_ks(
    int k0, int tid, const float* __restrict__ W6,
    const uint4* __restrict__ brickq, const float* __restrict__ volb,
    float* __restrict__ out, size_t out_base0,
    float bx, float by, float bz,
    float ax0, float ax1, float ax2,
    float ay0, float ay1, float ay2,
    float az0, float az1, float az2,
    int cx, int cy, int cz)
{
    #pragma unroll 1
    for (int it = 0; it < 2; it++) {
        int k = k0 + it*THREADS + tid;
        unsigned long long acc64[8];
        #pragma unroll
        for (int p = 0; p < 8; p++) acc64[p] = 0ull;

        float w0a = __ldg(W6 + k);
        float w1a = __ldg(W6 + KTOT + k);
        float w2a = __ldg(W6 + 2*KTOT + k);
        float w0b = __ldg(W6 + 3*KTOT + k);
        float w1b = __ldg(W6 + 4*KTOT + k);
        float w2b = __ldg(W6 + 5*KTOT + k);

        #pragma unroll
        for (int s = 0; s < 2; s++) {
            float w0 = s ? w0b : w0a;
            float w1 = s ? w1b : w1a;
            float w2 = s ? w2b : w2a;
            float px = fmaf(ax0, w0, fmaf(ax1, w1, fmaf(ax2, w2, bx)));
            float py = fmaf(ay0, w0, fmaf(ay1, w1, fmaf(ay2, w2, by)));
            float pz = fmaf(az0, w0, fmaf(az1, w1, fmaf(az2, w2, bz)));
            float fx = floorf(px), fy = floorf(py), fz = floorf(pz);
            float tx = px - fx, ty = py - fy, tz = pz - fz;
            int ix0 = (int)fx, iy0 = (int)fy, iz0 = (int)fz;
            int ix1 = ix0 + 1, iy1 = iy0 + 1, iz1 = iz0 + 1;
            float wx0 = 1.f - tx, wx1 = tx;
            float wy0 = 1.f - ty, wy1 = ty;
            float wz0 = 1.f - tz, wz1 = tz;
            float sg = s ? -1.f : 1.f;

            if (EDGE) {
                // clamp + zero first (keeps near-border samples hot)
                if ((unsigned)ix0 >= DIM) { wx0 = 0.f; ix0 = (ix0 < 0) ? 0 : DIM-1; }
                if ((unsigned)ix1 >= DIM) { wx1 = 0.f; ix1 = (ix1 < 0) ? 0 : DIM-1; }
                if ((unsigned)iy0 >= DIM) { wy0 = 0.f; iy0 = (iy0 < 0) ? 0 : DIM-1; }
                if ((unsigned)iy1 >= DIM) { wy1 = 0.f; iy1 = (iy1 < 0) ? 0 : DIM-1; }
                if ((unsigned)iz0 >= DIM) { wz0 = 0.f; iz0 = (iz0 < 0) ? 0 : DIM-1; }
                if ((unsigned)iz1 >= DIM) { wz1 = 0.f; iz1 = (iz1 < 0) ? 0 : DIM-1; }
            }

            int jx0 = ix0 - cx, jx1 = ix1 - cx;
            int jy0 = iy0 - cy, jy1 = iy1 - cy;
            int jz0 = iz0 - cz, jz1 = iz1 - cz;

            if (__builtin_expect((unsigned)(jx0|jx1|jy0|jy1|jz0|jz1) < NB, 1)) {
                float wzy00 = wz0*wy0*sg, wzy01 = wz0*wy1*sg;
                float wzy10 = wz1*wy0*sg, wzy11 = wz1*wy1*sg;
                int r00 = jz0*SZ + jy0*SY, r01 = jz0*SZ + jy1*SY;
                int r10 = jz1*SZ + jy0*SY, r11 = jz1*SZ + jy1*SY;
                int offs[8] = { r00+jx0, r00+jx1, r01+jx0, r01+jx1,
                                r10+jx0, r10+jx1, r11+jx0, r11+jx1 };
                float wgt[8] = { wzy00*wx0, wzy00*wx1, wzy01*wx0, wzy01*wx1,
                                 wzy10*wx0, wzy10*wx1, wzy11*wx0, wzy11*wx1 };
                brick_accum(brickq, offs, wgt, acc64);
            } else {
                // cold: re-applies clamps from scratch (no-op for EDGE-preclamped)
                cold_accum(volb, ix0, ix1, iy0, iy1, iz0, iz1,
                           wx0, wx1, wy0, wy1, wz0, wz1, sg, acc64);
            }
        }
        #pragma unroll
        for (int p = 0; p < 8; p++) {
            float lo, hi;
            asm("mov.b64 {%0, %1}, %2;" : "=f"(lo), "=f"(hi) : "l"(acc64[p]));
            __stcs(&out[out_base0 + (size_t)(2*p)   * (FEATS*KTOT) + k], lo);
            __stcs(&out[out_base0 + (size_t)(2*p+1) * (FEATS*KTOT) + k], hi);
        }
    }
}

__global__ void __launch_bounds__(THREADS, 3)
obelisk_kernel(const float* __restrict__ vol,
               const float* __restrict__ xyz,
               const float* __restrict__ Amat,
               const float* __restrict__ W6,
               float* __restrict__ out)
{
    __shared__ uint4 brickq[BRICK_E];   // 21KB static
    __shared__ float sP[12];

    const int tid  = threadIdx.x;
    const int blk  = blockIdx.x;
    const int pt   = blk >> 1;
    const int kh   = blk & 1;
    const int b    = pt >> 9;
    const int f    = pt & (FEATS - 1);
    const int k0   = kh * KPB;

    if (tid == 0) {
        float x0 = xyz[pt*3+0], x1 = xyz[pt*3+1], x2 = xyz[pt*3+2];
        sP[0] = (x0 + 1.f) * 48.f - 0.5f;
        sP[1] = (x1 + 1.f) * 48.f - 0.5f;
        sP[2] = (x2 + 1.f) * 48.f - 0.5f;
        const float* Ar = Amat + pt * 9;
        sP[3] = 48.f*Ar[6]; sP[4]  = 48.f*Ar[7]; sP[5]  = 48.f*Ar[8];  // x row
        sP[6] = 48.f*Ar[3]; sP[7]  = 48.f*Ar[4]; sP[8]  = 48.f*Ar[5];  // y row
        sP[9] = 48.f*Ar[0]; sP[10] = 48.f*Ar[1]; sP[11] = 48.f*Ar[2];  // z row
    }
    __syncthreads();

    const float bx = sP[0], by = sP[1], bz = sP[2];
    const float ax0 = sP[3], ax1 = sP[4],  ax2 = sP[5];
    const float ay0 = sP[6], ay1 = sP[7],  ay2 = sP[8];
    const float az0 = sP[9], az1 = sP[10], az2 = sP[11];

    // Center-anchored brick [c, c+7], clamped inside the volume. sigma(offset)~0.42
    // voxel; +/-3 margin covers ~7 sigma; per-(k,s) in-brick check + fp32 global
    // fallback guarantees correctness regardless.
    int cx = (int)floorf(bx) - 3; cx = min(max(cx, 0), DIM - NB);
    int cy = (int)floorf(by) - 3; cy = min(max(cy, 0), DIM - NB);
    int cz = (int)floorf(bz) - 3; cz = min(max(cz, 0), DIM - NB);
    const bool edge = (cx == 0) | (cx == DIM - NB) |
                      (cy == 0) | (cy == DIM - NB) |
                      (cz == 0) | (cz == DIM - NB);

    const float* volb = vol + (size_t)b * C16 * DHW;
    const size_t out_base0 = (((size_t)b * C16) * FEATS + f) * KTOT;

    // --- Brick load: 8x8x8 voxels x 2 channel-octets, fp16x8 (uint4) padded layout ---
    {
        const float* src = volb + (size_t)cz * HW + cy * DIM + cx;
        #pragma unroll
        for (int t = 0; t < (NOCT*NB*NB*NB) / THREADS; t++) {   // 4 iters
            int m = t * THREADS + tid;
            int x  = m & 7;
            int y  = (m >> 3) & 7;
            int z  = (m >> 6) & 7;
            int c8 = m >> 9;
            const float* s0 = src + (size_t)(8*c8) * DHW + z * HW + y * DIM + x;
            __half2 h0 = __floats2half2_rn(__ldg(s0),         __ldg(s0 + DHW));
            __half2 h1 = __floats2half2_rn(__ldg(s0 + 2*DHW), __ldg(s0 + 3*DHW));
            __half2 h2 = __floats2half2_rn(__ldg(s0 + 4*DHW), __ldg(s0 + 5*DHW));
            __half2 h3 = __floats2half2_rn(__ldg(s0 + 6*DHW), __ldg(s0 + 7*DHW));
            uint4 q;
            q.x = *reinterpret_cast<unsigned int*>(&h0);
            q.y = *reinterpret_cast<unsigned int*>(&h1);
            q.z = *reinterpret_cast<unsigned int*>(&h2);
            q.w = *reinterpret_cast<unsigned int*>(&h3);
            brickq[c8 * PSV + z * SZ + y * SY + x] = q;
        }
    }
    __syncthreads();

    if (edge) {
        run_ks<true>(k0, tid, W6, brickq, volb, out, out_base0,
                     bx, by, bz, ax0,ax1,ax2, ay0,ay1,ay2, az0,az1,az2, cx, cy, cz);
    } else {
        run_ks<false>(k0, tid, W6, brickq, volb, out, out_base0,
                      bx, by, bz, ax0,ax1,ax2, ay0,ay1,ay2, az0,az1,az2, cx, cy, cz);
    }
}

extern "C" void kernel_launch(void* const* d_in, const int* in_sizes, int n_in,
                              void* d_out, int out_size)
{
    const float* vol  = (const float*)d_in[0];  // [2,16,96,96,96]
    const float* xyz  = (const float*)d_in[1];  // [2,512,3]
    const float* Amat = (const float*)d_in[2];  // [1024,3,3]
    const float* W6   = (const float*)d_in[3];  // [6,1024]
    float* out = (float*)d_out;                 // [2, 16*512, 1024]

    const int nblocks = 2 * 2 * FEATS;          // 2048
    obelisk_kernel<<<nblocks, THREADS>>>(vol, xyz, Amat, W6, out);
}

// round 17
// speedup vs baseline: 1.2204x; 1.2204x over previous
#include <cuda_runtime.h>
#include <cuda_fp16.h>

#define THREADS 256
#define C16 16
#define DIM 96
#define HW (DIM*DIM)
#define DHW (DIM*DIM*DIM)
#define FEATS 512
#define KTOT 1024
#define KPB 512            // k per block (KSPLIT=2)
#define NB 8               // fixed brick edge
// padded strides in uint4 (16B) units: x=1, y=10, z=84
// bank-group(16B): (84*dz + 10*dy + dx) mod 8 = {4dz+2dy+dx} mod 8 -> never 0 for |d|<=1
#define SY 10
#define SZ 84
#define PSV (NB*SZ)        // 672 uint4 per channel-octet slab
#define NOCT 2             // 16 channels = 2 octets (uint4 = 4 x half2)
#define BRICK_E (NOCT*PSV) // 1344 uint4 = 21KB

// Main k-loop, specialized on whether the brick touches the volume border.
// EDGE: clamp-then-check (R15 flow) so near-border samples stay on the hot path.
// !EDGE (~74% of blocks): raw-index brick check, no clamp math on the hot path
// (in-brick => in-volume since the brick is interior). Cold path: R15's inline
// global-fp32 fallback, with clamping applied locally (identical numerics).
template<bool EDGE>
__device__ __forceinline__ void run_ks(
    int k0, int tid, const float* __restrict__ W6,
    const uint4* __restrict__ brickq, const float* __restrict__ volb,
    float* __restrict__ out, size_t out_base0,
    float bx, float by, float bz,
    float ax0, float ax1, float ax2,
    float ay0, float ay1, float ay2,
    float az0, float az1, float az2,
    int cx, int cy, int cz)
{
    #pragma unroll 1
    for (int it = 0; it < 2; it++) {
        int k = k0 + it*THREADS + tid;
        // 16 fp32 accumulators held as 8 packed f32x2 (64-bit) regs
        unsigned long long acc64[8];
        #pragma unroll
        for (int p = 0; p < 8; p++) acc64[p] = 0ull;

        // load all 6 offset weights up front (batch both LDG latencies)
        float w0a = __ldg(W6 + k);
        float w1a = __ldg(W6 + KTOT + k);
        float w2a = __ldg(W6 + 2*KTOT + k);
        float w0b = __ldg(W6 + 3*KTOT + k);
        float w1b = __ldg(W6 + 4*KTOT + k);
        float w2b = __ldg(W6 + 5*KTOT + k);

        #pragma unroll
        for (int s = 0; s < 2; s++) {
            float w0 = s ? w0b : w0a;
            float w1 = s ? w1b : w1a;
            float w2 = s ? w2b : w2a;
            float px = fmaf(ax0, w0, fmaf(ax1, w1, fmaf(ax2, w2, bx)));
            float py = fmaf(ay0, w0, fmaf(ay1, w1, fmaf(ay2, w2, by)));
            float pz = fmaf(az0, w0, fmaf(az1, w1, fmaf(az2, w2, bz)));
            float fx = floorf(px), fy = floorf(py), fz = floorf(pz);
            float tx = px - fx, ty = py - fy, tz = pz - fz;
            // absolute voxel indices
            int ix0 = (int)fx, iy0 = (int)fy, iz0 = (int)fz;
            int ix1 = ix0 + 1, iy1 = iy0 + 1, iz1 = iz0 + 1;
            float wx0 = 1.f - tx, wx1 = tx;
            float wy0 = 1.f - ty, wy1 = ty;
            float wz0 = 1.f - tz, wz1 = tz;
            float sg = s ? -1.f : 1.f;

            if (EDGE) {
                // out-of-VOLUME corners: zero weight + clamp into volume
                // (clamped index provably lands inside the clamped brick)
                if ((unsigned)ix0 >= DIM) { wx0 = 0.f; ix0 = (ix0 < 0) ? 0 : DIM-1; }
                if ((unsigned)ix1 >= DIM) { wx1 = 0.f; ix1 = (ix1 < 0) ? 0 : DIM-1; }
                if ((unsigned)iy0 >= DIM) { wy0 = 0.f; iy0 = (iy0 < 0) ? 0 : DIM-1; }
                if ((unsigned)iy1 >= DIM) { wy1 = 0.f; iy1 = (iy1 < 0) ? 0 : DIM-1; }
                if ((unsigned)iz0 >= DIM) { wz0 = 0.f; iz0 = (iz0 < 0) ? 0 : DIM-1; }
                if ((unsigned)iz1 >= DIM) { wz1 = 0.f; iz1 = (iz1 < 0) ? 0 : DIM-1; }
            }

            // brick-relative
            int jx0 = ix0 - cx, jx1 = ix1 - cx;
            int jy0 = iy0 - cy, jy1 = iy1 - cy;
            int jz0 = iz0 - cz, jz1 = iz1 - cz;

            if (__builtin_expect((unsigned)(jx0|jx1|jy0|jy1|jz0|jz1) < NB, 1)) {
                // ---- HOT: all 8 corners inside the smem brick ----
                float wzy00 = wz0*wy0*sg, wzy01 = wz0*wy1*sg;
                float wzy10 = wz1*wy0*sg, wzy11 = wz1*wy1*sg;
                int r00 = jz0*SZ + jy0*SY, r01 = jz0*SZ + jy1*SY;
                int r10 = jz1*SZ + jy0*SY, r11 = jz1*SZ + jy1*SY;
                int offs[8] = { r00+jx0, r00+jx1, r01+jx0, r01+jx1,
                                r10+jx0, r10+jx1, r11+jx0, r11+jx1 };
                float wgt[8] = { wzy00*wx0, wzy00*wx1, wzy01*wx0, wzy01*wx1,
                                 wzy10*wx0, wzy10*wx1, wzy11*wx0, wzy11*wx1 };
                #pragma unroll
                for (int j = 0; j < 8; j++) {
                    const uint4* pj = brickq + offs[j];   // one address per corner
                    unsigned long long w2pk;
                    unsigned int wbits = __float_as_uint(wgt[j]);
                    asm("mov.b64 %0, {%1, %1};" : "=l"(w2pk) : "r"(wbits));
                    #pragma unroll
                    for (int c8 = 0; c8 < NOCT; c8++) {   // LDS.128, immediate c8*PSV*16
                        uint4 q = pj[c8 * PSV];
                        __half2 h0 = *reinterpret_cast<__half2*>(&q.x);
                        __half2 h1 = *reinterpret_cast<__half2*>(&q.y);
                        __half2 h2 = *reinterpret_cast<__half2*>(&q.z);
                        __half2 h3 = *reinterpret_cast<__half2*>(&q.w);
                        float2 f0 = __half22float2(h0);
                        float2 f1 = __half22float2(h1);
                        float2 f2 = __half22float2(h2);
                        float2 f3 = __half22float2(h3);
                        unsigned long long v0, v1, v2, v3;
                        asm("mov.b64 %0, {%1, %2};" : "=l"(v0) : "f"(f0.x), "f"(f0.y));
                        asm("mov.b64 %0, {%1, %2};" : "=l"(v1) : "f"(f1.x), "f"(f1.y));
                        asm("mov.b64 %0, {%1, %2};" : "=l"(v2) : "f"(f2.x), "f"(f2.y));
                        asm("mov.b64 %0, {%1, %2};" : "=l"(v3) : "f"(f3.x), "f"(f3.y));
                        asm("fma.rn.f32x2 %0, %1, %2, %0;" : "+l"(acc64[4*c8])   : "l"(v0), "l"(w2pk));
                        asm("fma.rn.f32x2 %0, %1, %2, %0;" : "+l"(acc64[4*c8+1]) : "l"(v1), "l"(w2pk));
                        asm("fma.rn.f32x2 %0, %1, %2, %0;" : "+l"(acc64[4*c8+2]) : "l"(v2), "l"(w2pk));
                        asm("fma.rn.f32x2 %0, %1, %2, %0;" : "+l"(acc64[4*c8+3]) : "l"(v3), "l"(w2pk));
                    }
                }
            } else {
                // ---- COLD (~never): corner outside brick; fp32 global gather.
                // Apply (or re-apply) full volume clamping locally.
                if ((unsigned)ix0 >= DIM) { wx0 = 0.f; ix0 = (ix0 < 0) ? 0 : DIM-1; }
                if ((unsigned)ix1 >= DIM) { wx1 = 0.f; ix1 = (ix1 < 0) ? 0 : DIM-1; }
                if ((unsigned)iy0 >= DIM) { wy0 = 0.f; iy0 = (iy0 < 0) ? 0 : DIM-1; }
                if ((unsigned)iy1 >= DIM) { wy1 = 0.f; iy1 = (iy1 < 0) ? 0 : DIM-1; }
                if ((unsigned)iz0 >= DIM) { wz0 = 0.f; iz0 = (iz0 < 0) ? 0 : DIM-1; }
                if ((unsigned)iz1 >= DIM) { wz1 = 0.f; iz1 = (iz1 < 0) ? 0 : DIM-1; }
                float wzy00 = wz0*wy0*sg, wzy01 = wz0*wy1*sg;
                float wzy10 = wz1*wy0*sg, wzy11 = wz1*wy1*sg;
                float wgt[8] = { wzy00*wx0, wzy00*wx1, wzy01*wx0, wzy01*wx1,
                                 wzy10*wx0, wzy10*wx1, wzy11*wx0, wzy11*wx1 };
                float accf[C16];
                #pragma unroll
                for (int p = 0; p < 8; p++) {
                    float lo, hi;
                    asm("mov.b64 {%0, %1}, %2;" : "=f"(lo), "=f"(hi) : "l"(acc64[p]));
                    accf[2*p] = lo; accf[2*p+1] = hi;
                }
                int r00 = iz0*HW + iy0*DIM, r01 = iz0*HW + iy1*DIM;
                int r10 = iz1*HW + iy0*DIM, r11 = iz1*HW + iy1*DIM;
                int offs[8] = { r00+ix0, r00+ix1, r01+ix0, r01+ix1,
                                r10+ix0, r10+ix1, r11+ix0, r11+ix1 };
                #pragma unroll 1
                for (int j = 0; j < 8; j++) {
                    const float* pj = volb + offs[j];
                    float w = wgt[j];
                    #pragma unroll
                    for (int c = 0; c < C16; c++)
                        accf[c] = fmaf(w, __ldg(pj + (size_t)c * DHW), accf[c]);
                }
                #pragma unroll
                for (int p = 0; p < 8; p++)
                    asm("mov.b64 %0, {%1, %2};" : "=l"(acc64[p]) : "f"(accf[2*p]), "f"(accf[2*p+1]));
            }
        }
        #pragma unroll
        for (int p = 0; p < 8; p++) {
            float lo, hi;
            asm("mov.b64 {%0, %1}, %2;" : "=f"(lo), "=f"(hi) : "l"(acc64[p]));
            out[out_base0 + (size_t)(2*p)   * (FEATS*KTOT) + k] = lo;
            out[out_base0 + (size_t)(2*p+1) * (FEATS*KTOT) + k] = hi;
        }
    }
}

__global__ void __launch_bounds__(THREADS, 3)
obelisk_kernel(const float* __restrict__ vol,
               const float* __restrict__ xyz,
               const float* __restrict__ Amat,
               const float* __restrict__ W6,
               float* __restrict__ out)
{
    __shared__ uint4 brickq[BRICK_E];   // 21KB static
    __shared__ float sP[12];

    const int tid  = threadIdx.x;
    const int blk  = blockIdx.x;
    const int pt   = blk >> 1;
    const int kh   = blk & 1;
    const int b    = pt >> 9;
    const int f    = pt & (FEATS - 1);
    const int k0   = kh * KPB;

    if (tid == 0) {
        float x0 = xyz[pt*3+0], x1 = xyz[pt*3+1], x2 = xyz[pt*3+2];
        sP[0] = (x0 + 1.f) * 48.f - 0.5f;
        sP[1] = (x1 + 1.f) * 48.f - 0.5f;
        sP[2] = (x2 + 1.f) * 48.f - 0.5f;
        const float* Ar = Amat + pt * 9;
        sP[3] = 48.f*Ar[6]; sP[4]  = 48.f*Ar[7]; sP[5]  = 48.f*Ar[8];  // x row
        sP[6] = 48.f*Ar[3]; sP[7]  = 48.f*Ar[4]; sP[8]  = 48.f*Ar[5];  // y row
        sP[9] = 48.f*Ar[0]; sP[10] = 48.f*Ar[1]; sP[11] = 48.f*Ar[2];  // z row
    }
    __syncthreads();

    const float bx = sP[0], by = sP[1], bz = sP[2];
    const float ax0 = sP[3], ax1 = sP[4],  ax2 = sP[5];
    const float ay0 = sP[6], ay1 = sP[7],  ay2 = sP[8];
    const float az0 = sP[9], az1 = sP[10], az2 = sP[11];

    // Center-anchored brick [c, c+7], clamped inside the volume. sigma(offset)~0.42
    // voxel; +/-3 margin covers ~7 sigma; per-(k,s) in-brick check + fp32 global
    // fallback guarantees correctness regardless.
    int cx = (int)floorf(bx) - 3; cx = min(max(cx, 0), DIM - NB);
    int cy = (int)floorf(by) - 3; cy = min(max(cy, 0), DIM - NB);
    int cz = (int)floorf(bz) - 3; cz = min(max(cz, 0), DIM - NB);
    const bool edge = (cx == 0) | (cx == DIM - NB) |
                      (cy == 0) | (cy == DIM - NB) |
                      (cz == 0) | (cz == DIM - NB);

    const float* volb = vol + (size_t)b * C16 * DHW;
    const size_t out_base0 = (((size_t)b * C16) * FEATS + f) * KTOT;

    // --- Brick load: 8x8x8 voxels x 2 channel-octets, fp16x8 (uint4) padded layout ---
    {
        const float* src = volb + (size_t)cz * HW + cy * DIM + cx;
        #pragma unroll
        for (int t = 0; t < (NOCT*NB*NB*NB) / THREADS; t++) {   // 4 iters
            int m = t * THREADS + tid;
            int x  = m & 7;
            int y  = (m >> 3) & 7;
            int z  = (m >> 6) & 7;
            int c8 = m >> 9;
            const float* s0 = src + (size_t)(8*c8) * DHW + z * HW + y * DIM + x;
            __half2 h0 = __floats2half2_rn(__ldg(s0),         __ldg(s0 + DHW));
            __half2 h1 = __floats2half2_rn(__ldg(s0 + 2*DHW), __ldg(s0 + 3*DHW));
            __half2 h2 = __floats2half2_rn(__ldg(s0 + 4*DHW), __ldg(s0 + 5*DHW));
            __half2 h3 = __floats2half2_rn(__ldg(s0 + 6*DHW), __ldg(s0 + 7*DHW));
            uint4 q;
            q.x = *reinterpret_cast<unsigned int*>(&h0);
            q.y = *reinterpret_cast<unsigned int*>(&h1);
            q.z = *reinterpret_cast<unsigned int*>(&h2);
            q.w = *reinterpret_cast<unsigned int*>(&h3);
            brickq[c8 * PSV + z * SZ + y * SY + x] = q;
        }
    }
    __syncthreads();

    if (edge) {
        run_ks<true>(k0, tid, W6, brickq, volb, out, out_base0,
                     bx, by, bz, ax0,ax1,ax2, ay0,ay1,ay2, az0,az1,az2, cx, cy, cz);
    } else {
        run_ks<false>(k0, tid, W6, brickq, volb, out, out_base0,
                      bx, by, bz, ax0,ax1,ax2, ay0,ay1,ay2, az0,az1,az2, cx, cy, cz);
    }
}

extern "C" void kernel_launch(void* const* d_in, const int* in_sizes, int n_in,
                              void* d_out, int out_size)
{
    const float* vol  = (const float*)d_in[0];  // [2,16,96,96,96]
    const float* xyz  = (const float*)d_in[1];  // [2,512,3]
    const float* Amat = (const float*)d_in[2];  // [1024,3,3]
    const float* W6   = (const float*)d_in[3];  // [6,1024]
    float* out = (float*)d_out;                 // [2, 16*512, 1024]

    const int nblocks = 2 * 2 * FEATS;          // 2048
    obelisk_kernel<<<nblocks, THREADS>>>(vol, xyz, Amat, W6, out);
}